// round 15
// baseline (speedup 1.0000x reference)
#include <cuda_runtime.h>
#include <cstdint>

#define HDIM 2048
#define MTOT 16384
#define COMBINED_ELEMS (MTOT * HDIM)
#define W_ELEMS (HDIM * HDIM)

// Scratch (static __device__ — no allocation allowed)
__device__ __align__(256) uint32_t g_xtf[MTOT * HDIM];    // x tf32, [m][h] (A of gemm1)
__device__ __align__(256) uint32_t g_xtfT[HDIM * MTOT];   // x tf32, [h][m] (A of xtx)
__device__ __align__(256) uint32_t g_wfr[W_ELEMS];        // wsum tf32, FRAGMENT order (B of gemm1/hebbw)
__device__ __align__(256) uint32_t g_xfrT[HDIM * MTOT];   // xT tf32, FRAGMENT order (B of xtx)
__device__ __align__(256) float    g_G[W_ELEMS];          // G = x^T x, fp32
__device__ __align__(256) float    g_sx[HDIM];            // column sums of x
__device__ float g_sumsq;

// ---------------------------------------------------------------------------
// Helpers (baseline sm_80+ ISA only)
// ---------------------------------------------------------------------------
__device__ __forceinline__ uint32_t f2tf32(float f) {
    uint32_t r;
    asm("cvt.rna.tf32.f32 %0, %1;" : "=r"(r) : "f"(f));
    return r;
}

__device__ __forceinline__ void mma_tf32(float* d, const uint32_t* a,
                                         uint32_t b0, uint32_t b1) {
    asm volatile(
        "mma.sync.aligned.m16n8k8.row.col.f32.tf32.tf32.f32 "
        "{%0,%1,%2,%3}, {%4,%5,%6,%7}, {%8,%9}, {%0,%1,%2,%3};"
        : "+f"(d[0]), "+f"(d[1]), "+f"(d[2]), "+f"(d[3])
        : "r"(a[0]), "r"(a[1]), "r"(a[2]), "r"(a[3]), "r"(b0), "r"(b1));
}

#define LDSM_X4(d, addr) \
    asm volatile("ldmatrix.sync.aligned.m8n8.x4.shared.b16 {%0,%1,%2,%3}, [%4];" \
        : "=r"((d)[0]), "=r"((d)[1]), "=r"((d)[2]), "=r"((d)[3]) : "r"(addr))

__device__ __forceinline__ void cp16(uint32_t smem_addr, const void* gptr) {
    asm volatile("cp.async.cg.shared.global [%0], [%1], 16;"
                 :: "r"(smem_addr), "l"(gptr) : "memory");
}
__device__ __forceinline__ void cp_commit() {
    asm volatile("cp.async.commit_group;" ::: "memory");
}
__device__ __forceinline__ void cp_wait1() {
    asm volatile("cp.async.wait_group 1;" ::: "memory");
}
__device__ __forceinline__ void cp_wait0() {
    asm volatile("cp.async.wait_group 0;" ::: "memory");
}
__device__ __forceinline__ void red_add(float* gaddr, float v) {
    asm volatile("red.global.add.f32 [%0], %1;" :: "l"(gaddr), "f"(v) : "memory");
}

// ---------------------------------------------------------------------------
// Fragment-order layout: block (n16, k8) = 128 u32 at
//   [(n16_idx * K8tot + k8_idx) * 128 + lane*4 + q], where
//   q0 = B[n16+l/4][k8*8 + l%4], q1 = +4 in k, q2 = +8 in n, q3 = both.
// One LDG.128 per lane == one LDSM.x4 result (b-regs for two n8 tiles).
// ---------------------------------------------------------------------------

// Prologue: g_wfr = tf32(fixed+plastic) in fragment order; zero g_G/g_sx/g_sumsq
__global__ void prologue_kernel(const float* __restrict__ fw,
                                const float* __restrict__ pw) {
    int gid = blockIdx.x * blockDim.x + threadIdx.x;    // 0 .. W_ELEMS/4
    if (gid == 0) g_sumsq = 0.0f;
    if (gid < HDIM) g_sx[gid] = 0.0f;
    *reinterpret_cast<float4*>(&g_G[gid * 4]) = make_float4(0.f, 0.f, 0.f, 0.f);

    const int block = gid >> 5;          // 0 .. 32767
    const int lane  = gid & 31;
    const int K8W = HDIM / 8;            // 256
    const int n16 = (block / K8W) * 16;
    const int k8  = block % K8W;
    const int na = n16 + (lane >> 2), nb = na + 8;
    const int ka = k8 * 8 + (lane & 3), kb = ka + 4;
    uint4 o;
    o.x = f2tf32(fw[(size_t)na * HDIM + ka] + pw[(size_t)na * HDIM + ka]);
    o.y = f2tf32(fw[(size_t)na * HDIM + kb] + pw[(size_t)na * HDIM + kb]);
    o.z = f2tf32(fw[(size_t)nb * HDIM + ka] + pw[(size_t)nb * HDIM + ka]);
    o.w = f2tf32(fw[(size_t)nb * HDIM + kb] + pw[(size_t)nb * HDIM + kb]);
    *reinterpret_cast<uint4*>(&g_wfr[(size_t)block * 128 + lane * 4]) = o;
}

// Fused: read x once -> g_xtf [m][h], g_xtfT [h][m], g_xfrT (fragment order
// over n=h, k=m), and column sums g_sx
__global__ void xcvt_kernel(const float* __restrict__ X) {
    __shared__ uint32_t t[32][33];
    __shared__ float s_sx[8][32];
    const int bx = blockIdx.x * 32;   // h
    const int by = blockIdx.y * 32;   // m
    const int tx = threadIdx.x, ty = threadIdx.y;
    float part = 0.0f;
    #pragma unroll
    for (int j = 0; j < 32; j += 8) {
        float f = X[(size_t)(by + ty + j) * HDIM + bx + tx];
        part += f;
        uint32_t v = f2tf32(f);
        t[ty + j][tx] = v;
        g_xtf[(size_t)(by + ty + j) * HDIM + bx + tx] = v;
    }
    s_sx[ty][tx] = part;
    __syncthreads();
    #pragma unroll
    for (int j = 0; j < 32; j += 8)
        g_xtfT[(size_t)(bx + ty + j) * MTOT + by + tx] = t[tx][ty + j];
    if (ty == 0) {
        float s = 0.0f;
        #pragma unroll
        for (int j = 0; j < 8; j++) s += s_sx[j][tx];
        atomicAdd(&g_sx[bx + tx], s);
    }
    // fragment-order blocks: 2 n16 x 4 k8 per 32x32 tile; thread -> (b=ty, lane=tx)
    {
        const int K8X = MTOT / 8;         // 2048
        const int n16l = (ty & 1) * 16;
        const int k8l  = ty >> 1;
        const int hl = n16l + (tx >> 2);          // local h
        const int ml = k8l * 8 + (tx & 3);        // local m
        uint4 o;
        o.x = t[ml][hl];
        o.y = t[ml + 4][hl];
        o.z = t[ml][hl + 8];
        o.w = t[ml + 4][hl + 8];
        size_t blk = (size_t)(bx / 16 + (ty & 1)) * K8X + (by / 8 + (ty >> 1));
        *reinterpret_cast<uint4*>(&g_xfrT[blk * 128 + tx * 4]) = o;
    }
}

__global__ void scale_w_kernel(float* __restrict__ W) {
    float n = sqrtf(g_sumsq);
    float s = (n > 1.0f) ? (1.0f / n) : 1.0f;
    int i = (blockIdx.x * blockDim.x + threadIdx.x) * 4;
    float4 v = *reinterpret_cast<float4*>(&W[i]);
    v.x *= s; v.y *= s; v.z *= s; v.w *= s;
    *reinterpret_cast<float4*>(&W[i]) = v;
}

// ---------------------------------------------------------------------------
// GEMM mainloop: A staged via cp.async+LDSM (smem [row][k], stride 36),
// B loaded directly from fragment-order gmem via LDG.128 (no smem).
// 128x128 tile, 256 thr, KCH=32, 3-stage A pipeline, 8 warps = 4(m) x 2(n).
// ---------------------------------------------------------------------------
#define KCH 32
#define S1 36
#define A_MAT (128 * S1)                   // 4608 u32 per stage
#define G_SMEM_BYTES (3 * A_MAT * 4)       // 55296 B
#define XTX_SMEM_BYTES (128 * 132 * 4)     // 67584 B (epilogue transpose staging)
#define EPI_STRIDE 132

__device__ __forceinline__ void gemm_mainloop(
    const uint32_t* Aq, int lda, int Klen, int r0g,
    const uint32_t* Bfr, int K8tot, int k8base, int c0g,
    uint32_t shb, float acc[2][8][4])
{
    const int tid = threadIdx.x;
    const int lid = tid & 31;
    const int wid = tid >> 5;
    const int wm = wid & 3;
    const int wn = wid >> 2;
    const int nchunk = Klen / KCH;
    const int k8max = nchunk * 4 - 1;

    const uint32_t aoff0 =
        (uint32_t)((wm * 32 + ((lid >> 3) & 1) * 8 + (lid & 7)) * S1
                   + ((lid >> 4) & 1) * 4) * 4;
    const uint32_t aoff1 = aoff0 + 16 * S1 * 4;

    // B fragment pointers: 4 n16-blocks per warp (n range 64)
    const uint32_t* bp[4];
    {
        size_t n16i = (size_t)(c0g / 16 + wn * 4);
        #pragma unroll
        for (int t2 = 0; t2 < 4; t2++)
            bp[t2] = Bfr + ((n16i + t2) * K8tot + k8base) * 128 + lid * 4;
    }

    const int srow = tid >> 3;
    const int skq  = tid & 7;

    auto issueA = [&](int c) {
        const int s = c % 3;
        const uint32_t sa = shb + (uint32_t)(s * A_MAT) * 4;
        const int k0 = c * KCH;
        #pragma unroll
        for (int i = 0; i < 4; i++) {
            int row = srow + i * 32;
            cp16(sa + (uint32_t)(row * S1 + skq * 4) * 4,
                 &Aq[(size_t)(r0g + row) * lda + k0 + skq * 4]);
        }
        cp_commit();
    };

    issueA(0);
    issueA(1);

    uint4 bfr[2][4];
    #pragma unroll
    for (int t2 = 0; t2 < 4; t2++)
        bfr[0][t2] = __ldg(reinterpret_cast<const uint4*>(bp[t2]));

    for (int c = 0; c < nchunk; c++) {
        if (c >= nchunk - 2) cp_wait0(); else cp_wait1();
        __syncthreads();
        if (c + 2 < nchunk) issueA(c + 2);

        const uint32_t sa = shb + (uint32_t)((c % 3) * A_MAT) * 4;
        #pragma unroll
        for (int ks = 0; ks < 4; ks++) {
            const int p = ks & 1;
            uint32_t a0[4], a1[4];
            LDSM_X4(a0, sa + aoff0 + ks * 32);
            LDSM_X4(a1, sa + aoff1 + ks * 32);
            // prefetch next ks (clamped; redundant load at the very end)
            {
                int k8n = c * 4 + ks + 1;
                k8n = (k8n > k8max) ? k8max : k8n;
                #pragma unroll
                for (int t2 = 0; t2 < 4; t2++)
                    bfr[p ^ 1][t2] = __ldg(reinterpret_cast<const uint4*>(
                        bp[t2] + (size_t)k8n * 128));
            }
            #pragma unroll
            for (int t2 = 0; t2 < 4; t2++) {
                const uint4 b = bfr[p][t2];
                mma_tf32(acc[0][2 * t2],     a0, b.x, b.y);
                mma_tf32(acc[1][2 * t2],     a1, b.x, b.y);
                mma_tf32(acc[0][2 * t2 + 1], a0, b.z, b.w);
                mma_tf32(acc[1][2 * t2 + 1], a1, b.z, b.w);
            }
        }
    }
    __syncthreads();
}

#define ACC_INIT(acc) \
    _Pragma("unroll") \
    for (int i_ = 0; i_ < 2; i_++) \
        _Pragma("unroll") \
        for (int t_ = 0; t_ < 8; t_++) \
            _Pragma("unroll") \
            for (int q_ = 0; q_ < 4; q_++) acc[i_][t_][q_] = 0.0f;

// ---------------------------------------------------------------------------
// GEMM1: combined[m,n] = sum_k x[m,k]*wsum[n,k] + bias[n]
// ---------------------------------------------------------------------------
__global__ __launch_bounds__(256, 2)
void gemm1_mma(const float* __restrict__ bias,
               float* __restrict__ C) {
    extern __shared__ uint32_t sh[];
    const uint32_t shb = (uint32_t)__cvta_generic_to_shared(sh);

    const int tid = threadIdx.x;
    const int wid = tid >> 5;
    const int lid = tid & 31;
    const int wm = wid & 3;
    const int wn = wid >> 2;
    const int r = lid >> 2;
    const int cq = lid & 3;
    const int m0 = blockIdx.y * 128;
    const int n0 = blockIdx.x * 128;

    float acc[2][8][4];
    ACC_INIT(acc);

    gemm_mainloop(g_xtf, HDIM, HDIM, m0, g_wfr, HDIM / 8, 0, n0, shb, acc);

    #pragma unroll
    for (int i = 0; i < 2; i++) {
        int row = m0 + wm * 32 + 16 * i + r;
        #pragma unroll
        for (int t = 0; t < 8; t++) {
            int col = n0 + wn * 64 + 8 * t + 2 * cq;
            float2 bv = *reinterpret_cast<const float2*>(&bias[col]);
            size_t b0 = (size_t)row * HDIM + col;
            size_t b1 = (size_t)(row + 8) * HDIM + col;
            *reinterpret_cast<float2*>(&C[b0]) =
                make_float2(acc[i][t][0] + bv.x, acc[i][t][1] + bv.y);
            *reinterpret_cast<float2*>(&C[b1]) =
                make_float2(acc[i][t][2] + bv.x, acc[i][t][3] + bv.y);
        }
    }
}

// ---------------------------------------------------------------------------
// XTX: G = x^T x (symmetric). 136 upper-tri tiles x 2 K-splits, RED accumulate.
// ---------------------------------------------------------------------------
__global__ __launch_bounds__(256, 2)
void xtx_mma() {
    extern __shared__ uint32_t sh[];
    const uint32_t shb = (uint32_t)__cvta_generic_to_shared(sh);

    const int tid = threadIdx.x;
    const int wid = tid >> 5;
    const int lid = tid & 31;
    const int wm = wid & 3;
    const int wn = wid >> 2;
    const int r = lid >> 2;
    const int cq = lid & 3;

    const int split = blockIdx.x & 1;
    int rem = blockIdx.x >> 1;
    int bi = 0;
    #pragma unroll 1
    while (rem >= 16 - bi) { rem -= 16 - bi; bi++; }
    const int bj = bi + rem;
    const int i0 = bi * 128;
    const int j0 = bj * 128;

    float acc[2][8][4];
    ACC_INIT(acc);

    gemm_mainloop(g_xtfT + split * (MTOT / 2), MTOT, MTOT / 2, i0,
                  g_xfrT, MTOT / 8, split * (MTOT / 2 / 8), j0, shb, acc);

    #pragma unroll
    for (int i = 0; i < 2; i++) {
        int row = i0 + wm * 32 + 16 * i + r;
        #pragma unroll
        for (int t = 0; t < 8; t++) {
            int col = j0 + wn * 64 + 8 * t + 2 * cq;
            red_add(&g_G[(size_t)row * HDIM + col],     acc[i][t][0]);
            red_add(&g_G[(size_t)row * HDIM + col + 1], acc[i][t][1]);
            red_add(&g_G[(size_t)(row + 8) * HDIM + col],     acc[i][t][2]);
            red_add(&g_G[(size_t)(row + 8) * HDIM + col + 1], acc[i][t][3]);
        }
    }

    if (bi == bj) return;

    float* st = reinterpret_cast<float*>(sh);
    #pragma unroll
    for (int i = 0; i < 2; i++) {
        int rl = wm * 32 + 16 * i + r;
        #pragma unroll
        for (int t = 0; t < 8; t++) {
            int cl = wn * 64 + 8 * t + 2 * cq;
            st[cl * EPI_STRIDE + rl]           = acc[i][t][0];
            st[(cl + 1) * EPI_STRIDE + rl]     = acc[i][t][1];
            st[cl * EPI_STRIDE + rl + 8]       = acc[i][t][2];
            st[(cl + 1) * EPI_STRIDE + rl + 8] = acc[i][t][3];
        }
    }
    __syncthreads();
    #pragma unroll
    for (int it = 0; it < 16; it++) {
        int slot = tid + (it << 8);
        int col = slot >> 5, mq = slot & 31;
        float4 v = *reinterpret_cast<const float4*>(&st[col * EPI_STRIDE + mq * 4]);
        float* gp = &g_G[(size_t)(j0 + col) * HDIM + i0 + mq * 4];
        red_add(gp + 0, v.x);
        red_add(gp + 1, v.y);
        red_add(gp + 2, v.z);
        red_add(gp + 3, v.w);
    }
}

// ---------------------------------------------------------------------------
// HEBBW: new_w = plastic + pf/M * (G @ wsum^T + sx (x) b); accumulate sumsq
// ---------------------------------------------------------------------------
__global__ __launch_bounds__(256, 2)
void hebbw_mma(const float* __restrict__ plastic,
               const float* __restrict__ prate,
               const float* __restrict__ hstr,
               const float* __restrict__ bias,
               float* __restrict__ Wout) {
    extern __shared__ uint32_t sh[];
    const uint32_t shb = (uint32_t)__cvta_generic_to_shared(sh);

    const int tid = threadIdx.x;
    const int wid = tid >> 5;
    const int lid = tid & 31;
    const int wm = wid & 3;
    const int wn = wid >> 2;
    const int r = lid >> 2;
    const int cq = lid & 3;
    const int i0 = blockIdx.y * 128;
    const int j0 = blockIdx.x * 128;

    float acc[2][8][4];
    ACC_INIT(acc);

    gemm_mainloop(reinterpret_cast<const uint32_t*>(g_G), HDIM, HDIM, i0,
                  g_wfr, HDIM / 8, 0, j0, shb, acc);

    const float pf = __ldg(&prate[0]) * __ldg(&hstr[0]) * (1.0f / (float)MTOT);
    float ss = 0.0f;
    #pragma unroll
    for (int i = 0; i < 2; i++) {
        int row = i0 + wm * 32 + 16 * i + r;
        float sx0 = g_sx[row], sx1 = g_sx[row + 8];
        #pragma unroll
        for (int t = 0; t < 8; t++) {
            int col = j0 + wn * 64 + 8 * t + 2 * cq;
            float2 bv = *reinterpret_cast<const float2*>(&bias[col]);
            size_t b0 = (size_t)row * HDIM + col;
            size_t b1 = (size_t)(row + 8) * HDIM + col;
            float2 p0 = *reinterpret_cast<const float2*>(&plastic[b0]);
            float2 p1 = *reinterpret_cast<const float2*>(&plastic[b1]);
            float2 o0, o1;
            o0.x = p0.x + pf * (acc[i][t][0] + sx0 * bv.x);
            o0.y = p0.y + pf * (acc[i][t][1] + sx0 * bv.y);
            o1.x = p1.x + pf * (acc[i][t][2] + sx1 * bv.x);
            o1.y = p1.y + pf * (acc[i][t][3] + sx1 * bv.y);
            *reinterpret_cast<float2*>(&Wout[b0]) = o0;
            *reinterpret_cast<float2*>(&Wout[b1]) = o1;
            ss += o0.x * o0.x + o0.y * o0.y + o1.x * o1.x + o1.y * o1.y;
        }
    }
    #pragma unroll
    for (int s = 16; s > 0; s >>= 1)
        ss += __shfl_xor_sync(0xFFFFFFFFu, ss, s);
    if (lid == 0) atomicAdd(&g_sumsq, ss);
}

// ---------------------------------------------------------------------------
// Launch
// ---------------------------------------------------------------------------
extern "C" void kernel_launch(void* const* d_in, const int* in_sizes, int n_in,
                              void* d_out, int out_size) {
    const float* x       = (const float*)d_in[0];
    const float* plastic = (const float*)d_in[1];
    const float* prate   = (const float*)d_in[2];
    const float* fixed_w = (const float*)d_in[3];
    const float* fixed_b = (const float*)d_in[4];
    const float* hstr    = (const float*)d_in[5];

    float* combined = (float*)d_out;
    float* new_w    = (float*)d_out + COMBINED_ELEMS;

    static bool attr_done = false;
    if (!attr_done) {
        cudaFuncSetAttribute(gemm1_mma,
            cudaFuncAttributeMaxDynamicSharedMemorySize, G_SMEM_BYTES);
        cudaFuncSetAttribute(xtx_mma,
            cudaFuncAttributeMaxDynamicSharedMemorySize, XTX_SMEM_BYTES);
        cudaFuncSetAttribute(hebbw_mma,
            cudaFuncAttributeMaxDynamicSharedMemorySize, G_SMEM_BYTES);
        attr_done = true;
    }

    prologue_kernel<<<W_ELEMS / 4 / 256, 256>>>(fixed_w, plastic);
    xcvt_kernel<<<dim3(HDIM / 32, MTOT / 32), dim3(32, 8)>>>(x);

    xtx_mma<<<272, 256, XTX_SMEM_BYTES>>>();

    gemm1_mma<<<dim3(HDIM / 128, MTOT / 128), 256, G_SMEM_BYTES>>>(
        fixed_b, combined);

    hebbw_mma<<<dim3(HDIM / 128, HDIM / 128), 256, G_SMEM_BYTES>>>(
        plastic, prate, hstr, fixed_b, new_w);

    scale_w_kernel<<<W_ELEMS / 4 / 256, 256>>>(new_w);
}